// round 9
// baseline (speedup 1.0000x reference)
#include <cuda_runtime.h>
#include <math.h>
#include <stdint.h>

// Problem shape (fixed)
#define BB 256
#define TT 256
#define CC 512
#define HH 64

// Scratch for projections (device globals: no allocation allowed)
__device__ float g_q[BB * TT * HH];
__device__ float g_k[BB * TT * HH];
__device__ float g_v[BB * TT * HH];

__device__ __forceinline__ unsigned f2tf32(float f) {
    unsigned r;
    asm("cvt.rna.tf32.f32 %0, %1;" : "=r"(r) : "f"(f));
    return r;
}

__device__ __forceinline__ float ex2(float x) {
    float r;
    asm("ex2.approx.ftz.f32 %0, %1;" : "=f"(r) : "f"(x));
    return r;
}

__device__ __forceinline__ void mma_tf32(float c[4], const unsigned a[4], const unsigned b[2]) {
    asm volatile(
        "mma.sync.aligned.m16n8k8.row.col.f32.tf32.tf32.f32 "
        "{%0,%1,%2,%3}, {%4,%5,%6,%7}, {%8,%9}, {%0,%1,%2,%3};\n"
        : "+f"(c[0]), "+f"(c[1]), "+f"(c[2]), "+f"(c[3])
        : "r"(a[0]), "r"(a[1]), "r"(a[2]), "r"(a[3]), "r"(b[0]), "r"(b[1]));
}

__device__ __forceinline__ void cp_async16(void* smem_dst, const void* gmem_src) {
    uint32_t d = (uint32_t)__cvta_generic_to_shared(smem_dst);
    asm volatile("cp.async.cg.shared.global [%0], [%1], 16;\n" :: "r"(d), "l"(gmem_src));
}
__device__ __forceinline__ void cp_commit() { asm volatile("cp.async.commit_group;\n"); }

// ---------------------------------------------------------------------------
// Projection GEMM (R5 body): tf32 mma.sync, cp.async 2-stage, cvt at fragment
// load. R8 deltas: ONE sync per k-tile (wait -> sync -> prefetch -> compute)
// and __launch_bounds__(256,3) occupancy pin on the kernel.
// ---------------------------------------------------------------------------
template <int BN>
__device__ __forceinline__ void proj_body(const float* __restrict__ A,
                                          const float* __restrict__ W0,
                                          const float* __restrict__ W1,
                                          float* __restrict__ C0,
                                          float* __restrict__ C1,
                                          int blk) {
    constexpr int APITCH = 36;
    constexpr int BPITCH = BN + 4;
    constexpr int WN = BN / 2;
    constexpr int NT = WN / 8;
    constexpr int NK = CC / 32;
    constexpr int BC = (32 * BN / 4) / 256;

    extern __shared__ float smraw[];
    float* Asf = smraw;                        // [2][128][APITCH]
    float* Bsf = smraw + 2 * 128 * APITCH;     // [2][32][BPITCH]

    const int tid = threadIdx.x;
    const int wid = tid >> 5;
    const int lane = tid & 31;
    const int wm = wid & 3;
    const int wn = wid >> 2;
    const int g = lane >> 2;
    const int tig = lane & 3;
    const int m0 = blk * 128;

    auto load_tile = [&](int st, int k0) {
        float* As = Asf + st * 128 * APITCH;
        float* Bs = Bsf + st * 32 * BPITCH;
#pragma unroll
        for (int l = 0; l < 4; l++) {
            int idx = tid + l * 256;
            int r = idx >> 3;
            int c4 = (idx & 7) << 2;
            cp_async16(&As[r * APITCH + c4], &A[(size_t)(m0 + r) * CC + k0 + c4]);
        }
#pragma unroll
        for (int l = 0; l < BC; l++) {
            int idx = tid + l * 256;
            int r = idx / (BN / 4);
            int cc = (idx % (BN / 4)) << 2;
            const float* Wsrc = (cc < 64) ? W0 : W1;
            int wc = (cc < 64) ? cc : cc - 64;
            cp_async16(&Bs[r * BPITCH + cc], &Wsrc[(size_t)(k0 + r) * HH + wc]);
        }
        cp_commit();
    };

    float c[2][NT][4];
#pragma unroll
    for (int mt = 0; mt < 2; mt++)
#pragma unroll
        for (int nt = 0; nt < NT; nt++)
#pragma unroll
            for (int i = 0; i < 4; i++) c[mt][nt][i] = 0.0f;

    load_tile(0, 0);

    for (int t = 0; t < NK; t++) {
        // Only load(t) is outstanding here: wait it, barrier once, then
        // prefetch t+1 (into the buffer last touched at t-1, already synced)
        // and compute t while t+1 flies.
        asm volatile("cp.async.wait_group 0;\n");
        __syncthreads();
        if (t + 1 < NK) load_tile((t + 1) & 1, (t + 1) * 32);

        const float* As = Asf + (t & 1) * 128 * APITCH;
        const float* Bs = Bsf + (t & 1) * 32 * BPITCH;

#pragma unroll
        for (int ks = 0; ks < 4; ks++) {
            const int kb = ks * 8;
            unsigned af[2][4];
#pragma unroll
            for (int mt = 0; mt < 2; mt++) {
                int r = wm * 32 + mt * 16;
                af[mt][0] = f2tf32(As[(r + g) * APITCH + kb + tig]);
                af[mt][1] = f2tf32(As[(r + g + 8) * APITCH + kb + tig]);
                af[mt][2] = f2tf32(As[(r + g) * APITCH + kb + tig + 4]);
                af[mt][3] = f2tf32(As[(r + g + 8) * APITCH + kb + tig + 4]);
            }
            unsigned bf[NT][2];
#pragma unroll
            for (int nt = 0; nt < NT; nt++) {
                int cb = wn * WN + nt * 8;
                bf[nt][0] = f2tf32(Bs[(kb + tig) * BPITCH + cb + g]);
                bf[nt][1] = f2tf32(Bs[(kb + tig + 4) * BPITCH + cb + g]);
            }
#pragma unroll
            for (int mt = 0; mt < 2; mt++)
#pragma unroll
                for (int nt = 0; nt < NT; nt++) mma_tf32(c[mt][nt], af[mt], bf[nt]);
        }
    }

#pragma unroll
    for (int mt = 0; mt < 2; mt++) {
#pragma unroll
        for (int nt = 0; nt < NT; nt++) {
            int gcol = wn * WN + nt * 8 + 2 * tig;
            float* dst;
            int col;
            if (BN == 64) { dst = C0; col = gcol; }
            else { dst = (gcol < 64) ? C0 : C1; col = (gcol < 64) ? gcol : gcol - 64; }
            int row = m0 + wm * 32 + mt * 16 + g;
            *(float2*)&dst[(size_t)row * HH + col] = make_float2(c[mt][nt][0], c[mt][nt][1]);
            *(float2*)&dst[(size_t)(row + 8) * HH + col] = make_float2(c[mt][nt][2], c[mt][nt][3]);
        }
    }
}

// Merged launch: blocks [0,512) do q = x@Wq; blocks [512,1024) do [k|v] = y@[Wk|Wv].
__global__ __launch_bounds__(256, 3) void proj_all_kernel(const float* __restrict__ x,
                                                          const float* __restrict__ y,
                                                          const float* __restrict__ Wq,
                                                          const float* __restrict__ Wk,
                                                          const float* __restrict__ Wv,
                                                          float* __restrict__ gq,
                                                          float* __restrict__ gk,
                                                          float* __restrict__ gv) {
    if (blockIdx.x < 512) proj_body<64>(x, Wq, Wq, gq, gq, blockIdx.x);
    else                  proj_body<128>(y, Wk, Wv, gk, gv, blockIdx.x - 512);
}

// ---------------------------------------------------------------------------
// Flash attention (byte-identical to R5): tf32 mma.sync, chunked K/V cp.async
// double buffer, Q fragments in registers, 2 CTAs/SM.
// ---------------------------------------------------------------------------
#define KP 68
#define VP 72
#define PP 68
#define CHK 64

__global__ __launch_bounds__(256, 2) void attn_kernel(float* __restrict__ out) {
    extern __shared__ float sm[];
    float* Ks = sm;
    float* Vs = Ks + 2 * CHK * KP;
    float* Ps = Vs + 2 * CHK * VP;

    const int bx = blockIdx.x;
    const int b = bx >> 1;
    const int q0 = (bx & 1) * 128;
    const int tid = threadIdx.x;
    const int w = tid >> 5;
    const int lane = tid & 31;
    const int g = lane >> 2;
    const int tig = lane & 3;

    const float* __restrict__ Kg = g_k + (size_t)b * TT * HH;
    const float* __restrict__ Vg = g_v + (size_t)b * TT * HH;
    const float* __restrict__ Qg = g_q + (size_t)b * TT * HH;
    float* __restrict__ ob = out + (size_t)b * TT * HH;

    auto stage_load = [&](int ch) {
        float* Kc = Ks + (ch & 1) * CHK * KP;
        float* Vc = Vs + (ch & 1) * CHK * VP;
        const int s0 = ch * CHK;
#pragma unroll
        for (int l = 0; l < 4; l++) {
            int idx = tid + l * 256;
            int r = idx >> 4;
            int c4 = (idx & 15) << 2;
            cp_async16(&Kc[r * KP + c4], &Kg[(size_t)(s0 + r) * HH + c4]);
            cp_async16(&Vc[r * VP + c4], &Vg[(size_t)(s0 + r) * HH + c4]);
        }
        cp_commit();
    };

    stage_load(0);

    const int r0 = q0 + w * 16;
    const int rg0 = r0 + g;
    const int rg1 = r0 + g + 8;
    unsigned qf[8][4];
#pragma unroll
    for (int kc = 0; kc < 8; kc++) {
        const int kb = kc * 8;
        qf[kc][0] = f2tf32(Qg[(size_t)rg0 * HH + kb + tig]);
        qf[kc][1] = f2tf32(Qg[(size_t)rg1 * HH + kb + tig]);
        qf[kc][2] = f2tf32(Qg[(size_t)rg0 * HH + kb + tig + 4]);
        qf[kc][3] = f2tf32(Qg[(size_t)rg1 * HH + kb + tig + 4]);
    }

    float* Pw = Ps + w * 16 * PP;
    const float c2 = 0.125f * 1.44269504089f;

    float o[8][4];
#pragma unroll
    for (int nt = 0; nt < 8; nt++)
#pragma unroll
        for (int j = 0; j < 4; j++) o[nt][j] = 0.0f;

    float mt0 = -1e30f, mt1 = -1e30f;
    float l0 = 0.0f, l1 = 0.0f;

    const int CB = (q0 + 127) >> 6;
    const int cw = (r0 + 15) >> 6;

    for (int ch = 0; ch <= CB; ch++) {
        asm volatile("cp.async.wait_group 0;\n");
        __syncthreads();
        if (ch < CB) stage_load(ch + 1);

        {
            float* Kc = Ks + (ch & 1) * CHK * KP;
            float* Vc = Vs + (ch & 1) * CHK * VP;
#pragma unroll
            for (int l = 0; l < 4; l++) {
                int idx = tid + l * 256;
                int r = idx >> 4;
                int c4 = (idx & 15) << 2;
                float4 kv = *(float4*)&Kc[r * KP + c4];
                kv.x = __uint_as_float(f2tf32(kv.x));
                kv.y = __uint_as_float(f2tf32(kv.y));
                kv.z = __uint_as_float(f2tf32(kv.z));
                kv.w = __uint_as_float(f2tf32(kv.w));
                *(float4*)&Kc[r * KP + c4] = kv;
                float4 vv = *(float4*)&Vc[r * VP + c4];
                vv.x = __uint_as_float(f2tf32(vv.x));
                vv.y = __uint_as_float(f2tf32(vv.y));
                vv.z = __uint_as_float(f2tf32(vv.z));
                vv.w = __uint_as_float(f2tf32(vv.w));
                *(float4*)&Vc[r * VP + c4] = vv;
            }
        }
        __syncthreads();

        if (ch > cw) continue;

        const float* Kc = Ks + (ch & 1) * CHK * KP;
        const float* Vc = Vs + (ch & 1) * CHK * VP;
        const int s0 = ch * CHK;
        const int ntmax = min(7, (r0 + 15 - s0) >> 3);
        const bool full = (s0 + CHK - 1 <= r0);

        float sc[8][4];
#pragma unroll
        for (int nt = 0; nt < 8; nt++)
            if (nt <= ntmax) { sc[nt][0] = 0; sc[nt][1] = 0; sc[nt][2] = 0; sc[nt][3] = 0; }
#pragma unroll
        for (int kc = 0; kc < 8; kc++) {
            const int kb = kc * 8;
#pragma unroll
            for (int nt = 0; nt < 8; nt++) {
                if (nt <= ntmax) {
                    unsigned bfr[2];
                    int krow = nt * 8 + g;
                    bfr[0] = __float_as_uint(Kc[krow * KP + kb + tig]);
                    bfr[1] = __float_as_uint(Kc[krow * KP + kb + tig + 4]);
                    mma_tf32(sc[nt], qf[kc], bfr);
                }
            }
        }

        float cm0 = -1e30f, cm1 = -1e30f;
#pragma unroll
        for (int nt = 0; nt < 8; nt++) {
            if (nt <= ntmax) {
                if (full) {
                    sc[nt][0] *= c2; sc[nt][1] *= c2; sc[nt][2] *= c2; sc[nt][3] *= c2;
                } else {
                    const int colb = s0 + nt * 8 + 2 * tig;
                    sc[nt][0] = (colb <= rg0) ? sc[nt][0] * c2 : -1e30f;
                    sc[nt][1] = (colb + 1 <= rg0) ? sc[nt][1] * c2 : -1e30f;
                    sc[nt][2] = (colb <= rg1) ? sc[nt][2] * c2 : -1e30f;
                    sc[nt][3] = (colb + 1 <= rg1) ? sc[nt][3] * c2 : -1e30f;
                }
                cm0 = fmaxf(cm0, fmaxf(sc[nt][0], sc[nt][1]));
                cm1 = fmaxf(cm1, fmaxf(sc[nt][2], sc[nt][3]));
            }
        }
        cm0 = fmaxf(cm0, __shfl_xor_sync(0xffffffffu, cm0, 1));
        cm0 = fmaxf(cm0, __shfl_xor_sync(0xffffffffu, cm0, 2));
        cm1 = fmaxf(cm1, __shfl_xor_sync(0xffffffffu, cm1, 1));
        cm1 = fmaxf(cm1, __shfl_xor_sync(0xffffffffu, cm1, 2));

        const float nm0 = fmaxf(mt0, cm0);
        const float nm1 = fmaxf(mt1, cm1);
        const float f0 = ex2(mt0 - nm0);
        const float f1 = ex2(mt1 - nm1);
        mt0 = nm0; mt1 = nm1;
        l0 *= f0; l1 *= f1;
#pragma unroll
        for (int nt = 0; nt < 8; nt++) {
            o[nt][0] *= f0; o[nt][1] *= f0; o[nt][2] *= f1; o[nt][3] *= f1;
        }

        __syncwarp();
#pragma unroll
        for (int nt = 0; nt < 8; nt++) {
            if (nt <= ntmax) {
                float p0 = ex2(sc[nt][0] - nm0);
                float p1 = ex2(sc[nt][1] - nm0);
                float p2 = ex2(sc[nt][2] - nm1);
                float p3 = ex2(sc[nt][3] - nm1);
                l0 += p0 + p1;
                l1 += p2 + p3;
                int cb = nt * 8 + 2 * tig;
                *(float2*)&Pw[g * PP + cb] =
                    make_float2(__uint_as_float(f2tf32(p0)), __uint_as_float(f2tf32(p1)));
                *(float2*)&Pw[(g + 8) * PP + cb] =
                    make_float2(__uint_as_float(f2tf32(p2)), __uint_as_float(f2tf32(p3)));
            }
        }
        __syncwarp();

#pragma unroll
        for (int kc = 0; kc < 8; kc++) {
            if (kc <= ntmax) {
                const int kb = kc * 8;
                unsigned a[4];
                a[0] = __float_as_uint(Pw[g * PP + kb + tig]);
                a[1] = __float_as_uint(Pw[(g + 8) * PP + kb + tig]);
                a[2] = __float_as_uint(Pw[g * PP + kb + tig + 4]);
                a[3] = __float_as_uint(Pw[(g + 8) * PP + kb + tig + 4]);
                const int vr0 = kb + tig;
                const int vr1 = kb + tig + 4;
#pragma unroll
                for (int nt = 0; nt < 8; nt++) {
                    unsigned bfr[2];
                    bfr[0] = __float_as_uint(Vc[vr0 * VP + nt * 8 + g]);
                    bfr[1] = __float_as_uint(Vc[vr1 * VP + nt * 8 + g]);
                    mma_tf32(o[nt], a, bfr);
                }
            }
        }
    }

    l0 += __shfl_xor_sync(0xffffffffu, l0, 1);
    l0 += __shfl_xor_sync(0xffffffffu, l0, 2);
    l1 += __shfl_xor_sync(0xffffffffu, l1, 1);
    l1 += __shfl_xor_sync(0xffffffffu, l1, 2);
    const float inv0 = __frcp_rn(l0);
    const float inv1 = __frcp_rn(l1);

#pragma unroll
    for (int nt = 0; nt < 8; nt++) {
        int cb = nt * 8 + 2 * tig;
        *(float2*)&ob[(size_t)rg0 * HH + cb] = make_float2(o[nt][0] * inv0, o[nt][1] * inv0);
        *(float2*)&ob[(size_t)rg1 * HH + cb] = make_float2(o[nt][2] * inv1, o[nt][3] * inv1);
    }
}

// ---------------------------------------------------------------------------
extern "C" void kernel_launch(void* const* d_in, const int* in_sizes, int n_in,
                              void* d_out, int out_size) {
    const float* x = (const float*)d_in[0];
    const float* y = (const float*)d_in[1];
    const float* Wq = (const float*)d_in[2];
    const float* Wk = (const float*)d_in[3];
    const float* Wv = (const float*)d_in[4];
    float* out = (float*)d_out;

    float* gq;  cudaGetSymbolAddress((void**)&gq, g_q);
    float* gk;  cudaGetSymbolAddress((void**)&gk, g_k);
    float* gv;  cudaGetSymbolAddress((void**)&gv, g_v);

    const int smem_proj = (2 * 128 * 36 + 2 * 32 * 132) * 4;                   // 70656 -> 3 CTAs/SM
    const int smem_attn = (2 * CHK * KP + 2 * CHK * VP + 8 * 16 * PP) * 4;     // 106496

    static bool attr_set = false;
    if (!attr_set) {
        cudaFuncSetAttribute(proj_all_kernel, cudaFuncAttributeMaxDynamicSharedMemorySize, smem_proj);
        cudaFuncSetAttribute(attn_kernel, cudaFuncAttributeMaxDynamicSharedMemorySize, smem_attn);
        attr_set = true;
    }

    proj_all_kernel<<<1024, 256, smem_proj>>>(x, y, Wq, Wk, Wv, gq, gk, gv);
    attn_kernel<<<2 * BB, 256, smem_attn>>>(out);
}

// round 10
// speedup vs baseline: 1.4945x; 1.4945x over previous
#include <cuda_runtime.h>
#include <math.h>
#include <stdint.h>

// Problem shape (fixed)
#define BB 256
#define TT 256
#define CC 512
#define HH 64

// Scratch for projections (device globals: no allocation allowed)
__device__ float g_q[BB * TT * HH];
__device__ float g_k[BB * TT * HH];
__device__ float g_v[BB * TT * HH];

__device__ __forceinline__ unsigned f2tf32(float f) {
    unsigned r;
    asm("cvt.rna.tf32.f32 %0, %1;" : "=r"(r) : "f"(f));
    return r;
}

__device__ __forceinline__ float ex2(float x) {
    float r;
    asm("ex2.approx.ftz.f32 %0, %1;" : "=f"(r) : "f"(x));
    return r;
}

__device__ __forceinline__ void mma_tf32(float c[4], const unsigned a[4], const unsigned b[2]) {
    asm volatile(
        "mma.sync.aligned.m16n8k8.row.col.f32.tf32.tf32.f32 "
        "{%0,%1,%2,%3}, {%4,%5,%6,%7}, {%8,%9}, {%0,%1,%2,%3};\n"
        : "+f"(c[0]), "+f"(c[1]), "+f"(c[2]), "+f"(c[3])
        : "r"(a[0]), "r"(a[1]), "r"(a[2]), "r"(a[3]), "r"(b[0]), "r"(b[1]));
}

__device__ __forceinline__ void cp_async16(void* smem_dst, const void* gmem_src) {
    uint32_t d = (uint32_t)__cvta_generic_to_shared(smem_dst);
    asm volatile("cp.async.cg.shared.global [%0], [%1], 16;\n" :: "r"(d), "l"(gmem_src));
}
__device__ __forceinline__ void cp_commit() { asm volatile("cp.async.commit_group;\n"); }

// ---------------------------------------------------------------------------
// Projection GEMM body: tf32 mma.sync, cp.async 2-stage, R5 pipeline (two
// syncs, wait_group 1, cvt at fragment load). Templated tile:
//   BM=256,BN=64 : warp tile 64x32 (MT=4, NT=4)  -- q projection
//   BM=128,BN=128: warp tile 32x64 (MT=2, NT=8)  -- fused k|v projection
// ---------------------------------------------------------------------------
template <int BN, int BM>
__device__ __forceinline__ void proj_body(const float* __restrict__ A,
                                          const float* __restrict__ W0,
                                          const float* __restrict__ W1,
                                          float* __restrict__ C0,
                                          float* __restrict__ C1,
                                          int blk) {
    constexpr int APITCH = 36;
    constexpr int BPITCH = BN + 4;
    constexpr int MT = BM / 64;
    constexpr int WN = BN / 2;
    constexpr int NT = WN / 8;
    constexpr int NK = CC / 32;
    constexpr int BC = (32 * BN / 4) / 256;

    extern __shared__ float smraw[];
    float* Asf = smraw;                        // [2][BM][APITCH]
    float* Bsf = smraw + 2 * BM * APITCH;      // [2][32][BPITCH]

    const int tid = threadIdx.x;
    const int wid = tid >> 5;
    const int lane = tid & 31;
    const int wm = wid & 3;
    const int wn = wid >> 2;
    const int g = lane >> 2;
    const int tig = lane & 3;
    const int m0 = blk * BM;

    auto load_tile = [&](int st, int k0) {
        float* As = Asf + st * BM * APITCH;
        float* Bs = Bsf + st * 32 * BPITCH;
#pragma unroll
        for (int l = 0; l < BM / 32; l++) {
            int idx = tid + l * 256;
            int r = idx >> 3;
            int c4 = (idx & 7) << 2;
            cp_async16(&As[r * APITCH + c4], &A[(size_t)(m0 + r) * CC + k0 + c4]);
        }
#pragma unroll
        for (int l = 0; l < BC; l++) {
            int idx = tid + l * 256;
            int r = idx / (BN / 4);
            int cc = (idx % (BN / 4)) << 2;
            const float* Wsrc = (cc < 64) ? W0 : W1;
            int wc = (cc < 64) ? cc : cc - 64;
            cp_async16(&Bs[r * BPITCH + cc], &Wsrc[(size_t)(k0 + r) * HH + wc]);
        }
        cp_commit();
    };

    float c[MT][NT][4];
#pragma unroll
    for (int mt = 0; mt < MT; mt++)
#pragma unroll
        for (int nt = 0; nt < NT; nt++)
#pragma unroll
            for (int i = 0; i < 4; i++) c[mt][nt][i] = 0.0f;

    load_tile(0, 0);

    for (int t = 0; t < NK; t++) {
        if (t + 1 < NK) {
            load_tile((t + 1) & 1, (t + 1) * 32);
            asm volatile("cp.async.wait_group 1;\n");
        } else {
            asm volatile("cp.async.wait_group 0;\n");
        }
        __syncthreads();

        const float* As = Asf + (t & 1) * BM * APITCH;
        const float* Bs = Bsf + (t & 1) * 32 * BPITCH;

#pragma unroll
        for (int ks = 0; ks < 4; ks++) {
            const int kb = ks * 8;
            unsigned af[MT][4];
#pragma unroll
            for (int mt = 0; mt < MT; mt++) {
                int r = wm * (MT * 16) + mt * 16;
                af[mt][0] = f2tf32(As[(r + g) * APITCH + kb + tig]);
                af[mt][1] = f2tf32(As[(r + g + 8) * APITCH + kb + tig]);
                af[mt][2] = f2tf32(As[(r + g) * APITCH + kb + tig + 4]);
                af[mt][3] = f2tf32(As[(r + g + 8) * APITCH + kb + tig + 4]);
            }
            unsigned bf[NT][2];
#pragma unroll
            for (int nt = 0; nt < NT; nt++) {
                int cb = wn * WN + nt * 8;
                bf[nt][0] = f2tf32(Bs[(kb + tig) * BPITCH + cb + g]);
                bf[nt][1] = f2tf32(Bs[(kb + tig + 4) * BPITCH + cb + g]);
            }
#pragma unroll
            for (int mt = 0; mt < MT; mt++)
#pragma unroll
                for (int nt = 0; nt < NT; nt++) mma_tf32(c[mt][nt], af[mt], bf[nt]);
        }
        __syncthreads();
    }

#pragma unroll
    for (int mt = 0; mt < MT; mt++) {
#pragma unroll
        for (int nt = 0; nt < NT; nt++) {
            int gcol = wn * WN + nt * 8 + 2 * tig;
            float* dst;
            int col;
            if (BN == 64) { dst = C0; col = gcol; }
            else { dst = (gcol < 64) ? C0 : C1; col = (gcol < 64) ? gcol : gcol - 64; }
            int row = m0 + wm * (MT * 16) + mt * 16 + g;
            *(float2*)&dst[(size_t)row * HH + col] = make_float2(c[mt][nt][0], c[mt][nt][1]);
            *(float2*)&dst[(size_t)(row + 8) * HH + col] = make_float2(c[mt][nt][2], c[mt][nt][3]);
        }
    }
}

// q = x @ Wq : BM=256, one resident wave (grid 256, 2 CTA/SM)
__global__ __launch_bounds__(256) void proj_q_kernel(const float* __restrict__ x,
                                                     const float* __restrict__ Wq,
                                                     float* __restrict__ gq) {
    proj_body<64, 256>(x, Wq, Wq, gq, gq, blockIdx.x);
}

// [k|v] = y @ [Wk|Wv] : exact R5 shape (BM=128, 70.6KB smem)
__global__ __launch_bounds__(256) void proj_kv_kernel(const float* __restrict__ y,
                                                      const float* __restrict__ Wk,
                                                      const float* __restrict__ Wv,
                                                      float* __restrict__ gk,
                                                      float* __restrict__ gv) {
    proj_body<128, 128>(y, Wk, Wv, gk, gv, blockIdx.x);
}

// ---------------------------------------------------------------------------
// Flash attention (byte-identical to R5): tf32 mma.sync, chunked K/V cp.async
// double buffer, Q fragments in registers, 2 CTAs/SM.
// ---------------------------------------------------------------------------
#define KP 68
#define VP 72
#define PP 68
#define CHK 64

__global__ __launch_bounds__(256, 2) void attn_kernel(float* __restrict__ out) {
    extern __shared__ float sm[];
    float* Ks = sm;
    float* Vs = Ks + 2 * CHK * KP;
    float* Ps = Vs + 2 * CHK * VP;

    const int bx = blockIdx.x;
    const int b = bx >> 1;
    const int q0 = (bx & 1) * 128;
    const int tid = threadIdx.x;
    const int w = tid >> 5;
    const int lane = tid & 31;
    const int g = lane >> 2;
    const int tig = lane & 3;

    const float* __restrict__ Kg = g_k + (size_t)b * TT * HH;
    const float* __restrict__ Vg = g_v + (size_t)b * TT * HH;
    const float* __restrict__ Qg = g_q + (size_t)b * TT * HH;
    float* __restrict__ ob = out + (size_t)b * TT * HH;

    auto stage_load = [&](int ch) {
        float* Kc = Ks + (ch & 1) * CHK * KP;
        float* Vc = Vs + (ch & 1) * CHK * VP;
        const int s0 = ch * CHK;
#pragma unroll
        for (int l = 0; l < 4; l++) {
            int idx = tid + l * 256;
            int r = idx >> 4;
            int c4 = (idx & 15) << 2;
            cp_async16(&Kc[r * KP + c4], &Kg[(size_t)(s0 + r) * HH + c4]);
            cp_async16(&Vc[r * VP + c4], &Vg[(size_t)(s0 + r) * HH + c4]);
        }
        cp_commit();
    };

    stage_load(0);

    const int r0 = q0 + w * 16;
    const int rg0 = r0 + g;
    const int rg1 = r0 + g + 8;
    unsigned qf[8][4];
#pragma unroll
    for (int kc = 0; kc < 8; kc++) {
        const int kb = kc * 8;
        qf[kc][0] = f2tf32(Qg[(size_t)rg0 * HH + kb + tig]);
        qf[kc][1] = f2tf32(Qg[(size_t)rg1 * HH + kb + tig]);
        qf[kc][2] = f2tf32(Qg[(size_t)rg0 * HH + kb + tig + 4]);
        qf[kc][3] = f2tf32(Qg[(size_t)rg1 * HH + kb + tig + 4]);
    }

    float* Pw = Ps + w * 16 * PP;
    const float c2 = 0.125f * 1.44269504089f;

    float o[8][4];
#pragma unroll
    for (int nt = 0; nt < 8; nt++)
#pragma unroll
        for (int j = 0; j < 4; j++) o[nt][j] = 0.0f;

    float mt0 = -1e30f, mt1 = -1e30f;
    float l0 = 0.0f, l1 = 0.0f;

    const int CB = (q0 + 127) >> 6;
    const int cw = (r0 + 15) >> 6;

    for (int ch = 0; ch <= CB; ch++) {
        asm volatile("cp.async.wait_group 0;\n");
        __syncthreads();
        if (ch < CB) stage_load(ch + 1);

        {
            float* Kc = Ks + (ch & 1) * CHK * KP;
            float* Vc = Vs + (ch & 1) * CHK * VP;
#pragma unroll
            for (int l = 0; l < 4; l++) {
                int idx = tid + l * 256;
                int r = idx >> 4;
                int c4 = (idx & 15) << 2;
                float4 kv = *(float4*)&Kc[r * KP + c4];
                kv.x = __uint_as_float(f2tf32(kv.x));
                kv.y = __uint_as_float(f2tf32(kv.y));
                kv.z = __uint_as_float(f2tf32(kv.z));
                kv.w = __uint_as_float(f2tf32(kv.w));
                *(float4*)&Kc[r * KP + c4] = kv;
                float4 vv = *(float4*)&Vc[r * VP + c4];
                vv.x = __uint_as_float(f2tf32(vv.x));
                vv.y = __uint_as_float(f2tf32(vv.y));
                vv.z = __uint_as_float(f2tf32(vv.z));
                vv.w = __uint_as_float(f2tf32(vv.w));
                *(float4*)&Vc[r * VP + c4] = vv;
            }
        }
        __syncthreads();

        if (ch > cw) continue;

        const float* Kc = Ks + (ch & 1) * CHK * KP;
        const float* Vc = Vs + (ch & 1) * CHK * VP;
        const int s0 = ch * CHK;
        const int ntmax = min(7, (r0 + 15 - s0) >> 3);
        const bool full = (s0 + CHK - 1 <= r0);

        float sc[8][4];
#pragma unroll
        for (int nt = 0; nt < 8; nt++)
            if (nt <= ntmax) { sc[nt][0] = 0; sc[nt][1] = 0; sc[nt][2] = 0; sc[nt][3] = 0; }
#pragma unroll
        for (int kc = 0; kc < 8; kc++) {
            const int kb = kc * 8;
#pragma unroll
            for (int nt = 0; nt < 8; nt++) {
                if (nt <= ntmax) {
                    unsigned bfr[2];
                    int krow = nt * 8 + g;
                    bfr[0] = __float_as_uint(Kc[krow * KP + kb + tig]);
                    bfr[1] = __float_as_uint(Kc[krow * KP + kb + tig + 4]);
                    mma_tf32(sc[nt], qf[kc], bfr);
                }
            }
        }

        float cm0 = -1e30f, cm1 = -1e30f;
#pragma unroll
        for (int nt = 0; nt < 8; nt++) {
            if (nt <= ntmax) {
                if (full) {
                    sc[nt][0] *= c2; sc[nt][1] *= c2; sc[nt][2] *= c2; sc[nt][3] *= c2;
                } else {
                    const int colb = s0 + nt * 8 + 2 * tig;
                    sc[nt][0] = (colb <= rg0) ? sc[nt][0] * c2 : -1e30f;
                    sc[nt][1] = (colb + 1 <= rg0) ? sc[nt][1] * c2 : -1e30f;
                    sc[nt][2] = (colb <= rg1) ? sc[nt][2] * c2 : -1e30f;
                    sc[nt][3] = (colb + 1 <= rg1) ? sc[nt][3] * c2 : -1e30f;
                }
                cm0 = fmaxf(cm0, fmaxf(sc[nt][0], sc[nt][1]));
                cm1 = fmaxf(cm1, fmaxf(sc[nt][2], sc[nt][3]));
            }
        }
        cm0 = fmaxf(cm0, __shfl_xor_sync(0xffffffffu, cm0, 1));
        cm0 = fmaxf(cm0, __shfl_xor_sync(0xffffffffu, cm0, 2));
        cm1 = fmaxf(cm1, __shfl_xor_sync(0xffffffffu, cm1, 1));
        cm1 = fmaxf(cm1, __shfl_xor_sync(0xffffffffu, cm1, 2));

        const float nm0 = fmaxf(mt0, cm0);
        const float nm1 = fmaxf(mt1, cm1);
        const float f0 = ex2(mt0 - nm0);
        const float f1 = ex2(mt1 - nm1);
        mt0 = nm0; mt1 = nm1;
        l0 *= f0; l1 *= f1;
#pragma unroll
        for (int nt = 0; nt < 8; nt++) {
            o[nt][0] *= f0; o[nt][1] *= f0; o[nt][2] *= f1; o[nt][3] *= f1;
        }

        __syncwarp();
#pragma unroll
        for (int nt = 0; nt < 8; nt++) {
            if (nt <= ntmax) {
                float p0 = ex2(sc[nt][0] - nm0);
                float p1 = ex2(sc[nt][1] - nm0);
                float p2 = ex2(sc[nt][2] - nm1);
                float p3 = ex2(sc[nt][3] - nm1);
                l0 += p0 + p1;
                l1 += p2 + p3;
                int cb = nt * 8 + 2 * tig;
                *(float2*)&Pw[g * PP + cb] =
                    make_float2(__uint_as_float(f2tf32(p0)), __uint_as_float(f2tf32(p1)));
                *(float2*)&Pw[(g + 8) * PP + cb] =
                    make_float2(__uint_as_float(f2tf32(p2)), __uint_as_float(f2tf32(p3)));
            }
        }
        __syncwarp();

#pragma unroll
        for (int kc = 0; kc < 8; kc++) {
            if (kc <= ntmax) {
                const int kb = kc * 8;
                unsigned a[4];
                a[0] = __float_as_uint(Pw[g * PP + kb + tig]);
                a[1] = __float_as_uint(Pw[(g + 8) * PP + kb + tig]);
                a[2] = __float_as_uint(Pw[g * PP + kb + tig + 4]);
                a[3] = __float_as_uint(Pw[(g + 8) * PP + kb + tig + 4]);
                const int vr0 = kb + tig;
                const int vr1 = kb + tig + 4;
#pragma unroll
                for (int nt = 0; nt < 8; nt++) {
                    unsigned bfr[2];
                    bfr[0] = __float_as_uint(Vc[vr0 * VP + nt * 8 + g]);
                    bfr[1] = __float_as_uint(Vc[vr1 * VP + nt * 8 + g]);
                    mma_tf32(o[nt], a, bfr);
                }
            }
        }
    }

    l0 += __shfl_xor_sync(0xffffffffu, l0, 1);
    l0 += __shfl_xor_sync(0xffffffffu, l0, 2);
    l1 += __shfl_xor_sync(0xffffffffu, l1, 1);
    l1 += __shfl_xor_sync(0xffffffffu, l1, 2);
    const float inv0 = __frcp_rn(l0);
    const float inv1 = __frcp_rn(l1);

#pragma unroll
    for (int nt = 0; nt < 8; nt++) {
        int cb = nt * 8 + 2 * tig;
        *(float2*)&ob[(size_t)rg0 * HH + cb] = make_float2(o[nt][0] * inv0, o[nt][1] * inv0);
        *(float2*)&ob[(size_t)rg1 * HH + cb] = make_float2(o[nt][2] * inv1, o[nt][3] * inv1);
    }
}

// ---------------------------------------------------------------------------
extern "C" void kernel_launch(void* const* d_in, const int* in_sizes, int n_in,
                              void* d_out, int out_size) {
    const float* x = (const float*)d_in[0];
    const float* y = (const float*)d_in[1];
    const float* Wq = (const float*)d_in[2];
    const float* Wk = (const float*)d_in[3];
    const float* Wv = (const float*)d_in[4];
    float* out = (float*)d_out;

    float* gq;  cudaGetSymbolAddress((void**)&gq, g_q);
    float* gk;  cudaGetSymbolAddress((void**)&gk, g_k);
    float* gv;  cudaGetSymbolAddress((void**)&gv, g_v);

    const int smem_q  = (2 * 256 * 36 + 2 * 32 * 68) * 4;                      // 91136
    const int smem_kv = (2 * 128 * 36 + 2 * 32 * 132) * 4;                     // 70656
    const int smem_attn = (2 * CHK * KP + 2 * CHK * VP + 8 * 16 * PP) * 4;     // 106496

    static bool attr_set = false;
    if (!attr_set) {
        cudaFuncSetAttribute(proj_q_kernel, cudaFuncAttributeMaxDynamicSharedMemorySize, smem_q);
        cudaFuncSetAttribute(proj_kv_kernel, cudaFuncAttributeMaxDynamicSharedMemorySize, smem_kv);
        cudaFuncSetAttribute(attn_kernel, cudaFuncAttributeMaxDynamicSharedMemorySize, smem_attn);
        attr_set = true;
    }

    proj_q_kernel<<<256, 256, smem_q>>>(x, Wq, gq);
    proj_kv_kernel<<<512, 256, smem_kv>>>(y, Wk, Wv, gk, gv);
    attn_kernel<<<2 * BB, 256, smem_attn>>>(out);
}

// round 13
// speedup vs baseline: 1.7836x; 1.1934x over previous
#include <cuda_runtime.h>
#include <math.h>
#include <stdint.h>

// Problem shape (fixed)
#define BB 256
#define TT 256
#define CC 512
#define HH 64

// Scratch (device globals: no allocation allowed)
__device__ float g_q[BB * TT * HH];
__device__ float g_k[BB * TT * HH];
__device__ float g_v[BB * TT * HH];
// Fragment-order packed weights (rna-tf32 applied):
//   index ((k8 * NTC + ntile) * 32 + lane) * 2 + j
//   holds W^T[n = ntile*8 + (lane>>2)][k = k8*8 + (lane&3) + 4*j]
__device__ float g_wpq[64 * 8 * 32 * 2];     // q:  NTC=8  (N=64)
__device__ float g_wpkv[64 * 16 * 32 * 2];   // kv: NTC=16 (N=128)

__device__ __forceinline__ unsigned f2tf32(float f) {
    unsigned r;
    asm("cvt.rna.tf32.f32 %0, %1;" : "=r"(r) : "f"(f));
    return r;
}

__device__ __forceinline__ float ex2(float x) {
    float r;
    asm("ex2.approx.ftz.f32 %0, %1;" : "=f"(r) : "f"(x));
    return r;
}

__device__ __forceinline__ void mma_tf32(float c[4], const unsigned a[4], const unsigned b[2]) {
    asm volatile(
        "mma.sync.aligned.m16n8k8.row.col.f32.tf32.tf32.f32 "
        "{%0,%1,%2,%3}, {%4,%5,%6,%7}, {%8,%9}, {%0,%1,%2,%3};\n"
        : "+f"(c[0]), "+f"(c[1]), "+f"(c[2]), "+f"(c[3])
        : "r"(a[0]), "r"(a[1]), "r"(a[2]), "r"(a[3]), "r"(b[0]), "r"(b[1]));
}

__device__ __forceinline__ void cp_async16(void* smem_dst, const void* gmem_src) {
    uint32_t d = (uint32_t)__cvta_generic_to_shared(smem_dst);
    asm volatile("cp.async.cg.shared.global [%0], [%1], 16;\n" :: "r"(d), "l"(gmem_src));
}
__device__ __forceinline__ void cp_commit() { asm volatile("cp.async.commit_group;\n"); }

// ---------------------------------------------------------------------------
// Weight pack prepass: fragment-order, rna-tf32.
// ---------------------------------------------------------------------------
__global__ void wpack_kernel(const float* __restrict__ Wq,
                             const float* __restrict__ Wk,
                             const float* __restrict__ Wv) {
    const int nq = 64 * 8 * 32 * 2;       // 32768
    const int nkv = 64 * 16 * 32 * 2;     // 65536
    int i = blockIdx.x * 256 + threadIdx.x;
    for (; i < nq + nkv; i += gridDim.x * 256) {
        if (i < nq) {
            int j = i & 1;
            int lane = (i >> 1) & 31;
            int nt = (i >> 6) & 7;
            int k8 = i >> 9;
            int n = nt * 8 + (lane >> 2);
            int k = k8 * 8 + (lane & 3) + 4 * j;
            g_wpq[i] = __uint_as_float(f2tf32(Wq[k * 64 + n]));
        } else {
            int p = i - nkv == i - nkv ? i - nq : 0;
            int j = p & 1;
            int lane = (p >> 1) & 31;
            int nt = (p >> 6) & 15;
            int k8 = p >> 10;
            int n = nt * 8 + (lane >> 2);
            int k = k8 * 8 + (lane & 3) + 4 * j;
            float v = (n < 64) ? Wk[k * 64 + n] : Wv[k * 64 + (n - 64)];
            g_wpkv[p] = __uint_as_float(f2tf32(v));
        }
    }
}

// ---------------------------------------------------------------------------
// Projection GEMM: R5 pipeline (two syncs, wait_group 1), A staged row-major
// (cvt at fragment load), B staged in fragment order from g_wp* (linear
// cp.async; one LDS.64 per fragment, zero cvt).
// ---------------------------------------------------------------------------
template <int BN>
__device__ __forceinline__ void proj_body(const float* __restrict__ A,
                                          const float* __restrict__ WP,
                                          float* __restrict__ C0,
                                          float* __restrict__ C1,
                                          int blk) {
    constexpr int APITCH = 36;
    constexpr int NTC = BN / 8;            // n8-tiles per CTA (8 or 16)
    constexpr int WN = BN / 2;
    constexpr int NT = WN / 8;             // n8-tiles per warp (4 or 8)
    constexpr int NK = CC / 32;            // 16 k-tiles
    constexpr int BSTRIDE = 256 * NTC;     // floats per B stage (4 k8 * NTC * 64)
    constexpr int BCH = (BSTRIDE / 4) / 256;  // 16B chunks per thread (2 or 4)

    extern __shared__ float smraw[];
    float* Asf = smraw;                        // [2][128][APITCH]
    float* Bsf = smraw + 2 * 128 * APITCH;     // [2][BSTRIDE]

    const int tid = threadIdx.x;
    const int wid = tid >> 5;
    const int lane = tid & 31;
    const int wm = wid & 3;
    const int wn = wid >> 2;
    const int g = lane >> 2;
    const int tig = lane & 3;
    const int m0 = blk * 128;

    auto load_tile = [&](int st, int t) {
        float* As = Asf + st * 128 * APITCH;
        float* Bs = Bsf + st * BSTRIDE;
        const int k0 = t * 32;
#pragma unroll
        for (int l = 0; l < 4; l++) {
            int idx = tid + l * 256;
            int r = idx >> 3;
            int c4 = (idx & 7) << 2;
            cp_async16(&As[r * APITCH + c4], &A[(size_t)(m0 + r) * CC + k0 + c4]);
        }
        const float* src = WP + (size_t)t * BSTRIDE;
#pragma unroll
        for (int l = 0; l < BCH; l++) {
            int c = tid + l * 256;
            cp_async16(&Bs[c * 4], &src[c * 4]);
        }
        cp_commit();
    };

    float c[2][NT][4];
#pragma unroll
    for (int mt = 0; mt < 2; mt++)
#pragma unroll
        for (int nt = 0; nt < NT; nt++)
#pragma unroll
            for (int i = 0; i < 4; i++) c[mt][nt][i] = 0.0f;

    load_tile(0, 0);

    for (int t = 0; t < NK; t++) {
        if (t + 1 < NK) {
            load_tile((t + 1) & 1, t + 1);
            asm volatile("cp.async.wait_group 1;\n");
        } else {
            asm volatile("cp.async.wait_group 0;\n");
        }
        __syncthreads();

        const float* As = Asf + (t & 1) * 128 * APITCH;
        const float* Bs = Bsf + (t & 1) * BSTRIDE;

#pragma unroll
        for (int ks = 0; ks < 4; ks++) {
            const int kb = ks * 8;
            unsigned af[2][4];
#pragma unroll
            for (int mt = 0; mt < 2; mt++) {
                int r = wm * 32 + mt * 16;
                af[mt][0] = f2tf32(As[(r + g) * APITCH + kb + tig]);
                af[mt][1] = f2tf32(As[(r + g + 8) * APITCH + kb + tig]);
                af[mt][2] = f2tf32(As[(r + g) * APITCH + kb + tig + 4]);
                af[mt][3] = f2tf32(As[(r + g + 8) * APITCH + kb + tig + 4]);
            }
            unsigned bf[NT][2];
#pragma unroll
            for (int nt = 0; nt < NT; nt++) {
                int tile_n = wn * NT + nt;
                float2 b2 = *(const float2*)&Bs[((ks * NTC + tile_n) * 32 + lane) * 2];
                bf[nt][0] = __float_as_uint(b2.x);
                bf[nt][1] = __float_as_uint(b2.y);
            }
#pragma unroll
            for (int mt = 0; mt < 2; mt++)
#pragma unroll
                for (int nt = 0; nt < NT; nt++) mma_tf32(c[mt][nt], af[mt], bf[nt]);
        }
        __syncthreads();
    }

#pragma unroll
    for (int mt = 0; mt < 2; mt++) {
#pragma unroll
        for (int nt = 0; nt < NT; nt++) {
            int gcol = wn * WN + nt * 8 + 2 * tig;
            float* dst;
            int col;
            if (BN == 64) { dst = C0; col = gcol; }
            else { dst = (gcol < 64) ? C0 : C1; col = (gcol < 64) ? gcol : gcol - 64; }
            int row = m0 + wm * 32 + mt * 16 + g;
            *(float2*)&dst[(size_t)row * HH + col] = make_float2(c[mt][nt][0], c[mt][nt][1]);
            *(float2*)&dst[(size_t)(row + 8) * HH + col] = make_float2(c[mt][nt][2], c[mt][nt][3]);
        }
    }
}

// Merged: blocks [0,512) -> q = x@Wq; [512,1024) -> [k|v] = y@[Wk|Wv].
__global__ __launch_bounds__(256) void proj_all_kernel(const float* __restrict__ x,
                                                       const float* __restrict__ y,
                                                       const float* __restrict__ wpq,
                                                       const float* __restrict__ wpkv,
                                                       float* __restrict__ gq,
                                                       float* __restrict__ gk,
                                                       float* __restrict__ gv) {
    if (blockIdx.x < 512) proj_body<64>(x, wpq, gq, gq, blockIdx.x);
    else                  proj_body<128>(y, wpkv, gk, gv, blockIdx.x - 512);
}

// ---------------------------------------------------------------------------
// Flash attention (byte-identical to R5): tf32 mma.sync, chunked K/V cp.async
// double buffer, Q fragments in registers, 2 CTAs/SM.
// ---------------------------------------------------------------------------
#define KP 68
#define VP 72
#define PP 68
#define CHK 64

__global__ __launch_bounds__(256, 2) void attn_kernel(float* __restrict__ out) {
    extern __shared__ float sm[];
    float* Ks = sm;
    float* Vs = Ks + 2 * CHK * KP;
    float* Ps = Vs + 2 * CHK * VP;

    const int bx = blockIdx.x;
    const int b = bx >> 1;
    const int q0 = (bx & 1) * 128;
    const int tid = threadIdx.x;
    const int w = tid >> 5;
    const int lane = tid & 31;
    const int g = lane >> 2;
    const int tig = lane & 3;

    const float* __restrict__ Kg = g_k + (size_t)b * TT * HH;
    const float* __restrict__ Vg = g_v + (size_t)b * TT * HH;
    const float* __restrict__ Qg = g_q + (size_t)b * TT * HH;
    float* __restrict__ ob = out + (size_t)b * TT * HH;

    auto stage_load = [&](int ch) {
        float* Kc = Ks + (ch & 1) * CHK * KP;
        float* Vc = Vs + (ch & 1) * CHK * VP;
        const int s0 = ch * CHK;
#pragma unroll
        for (int l = 0; l < 4; l++) {
            int idx = tid + l * 256;
            int r = idx >> 4;
            int c4 = (idx & 15) << 2;
            cp_async16(&Kc[r * KP + c4], &Kg[(size_t)(s0 + r) * HH + c4]);
            cp_async16(&Vc[r * VP + c4], &Vg[(size_t)(s0 + r) * HH + c4]);
        }
        cp_commit();
    };

    stage_load(0);

    const int r0 = q0 + w * 16;
    const int rg0 = r0 + g;
    const int rg1 = r0 + g + 8;
    unsigned qf[8][4];
#pragma unroll
    for (int kc = 0; kc < 8; kc++) {
        const int kb = kc * 8;
        qf[kc][0] = f2tf32(Qg[(size_t)rg0 * HH + kb + tig]);
        qf[kc][1] = f2tf32(Qg[(size_t)rg1 * HH + kb + tig]);
        qf[kc][2] = f2tf32(Qg[(size_t)rg0 * HH + kb + tig + 4]);
        qf[kc][3] = f2tf32(Qg[(size_t)rg1 * HH + kb + tig + 4]);
    }

    float* Pw = Ps + w * 16 * PP;
    const float c2 = 0.125f * 1.44269504089f;

    float o[8][4];
#pragma unroll
    for (int nt = 0; nt < 8; nt++)
#pragma unroll
        for (int j = 0; j < 4; j++) o[nt][j] = 0.0f;

    float mt0 = -1e30f, mt1 = -1e30f;
    float l0 = 0.0f, l1 = 0.0f;

    const int CB = (q0 + 127) >> 6;
    const int cw = (r0 + 15) >> 6;

    for (int ch = 0; ch <= CB; ch++) {
        asm volatile("cp.async.wait_group 0;\n");
        __syncthreads();
        if (ch < CB) stage_load(ch + 1);

        {
            float* Kc = Ks + (ch & 1) * CHK * KP;
            float* Vc = Vs + (ch & 1) * CHK * VP;
#pragma unroll
            for (int l = 0; l < 4; l++) {
                int idx = tid + l * 256;
                int r = idx >> 4;
                int c4 = (idx & 15) << 2;
                float4 kv = *(float4*)&Kc[r * KP + c4];
                kv.x = __uint_as_float(f2tf32(kv.x));
                kv.y = __uint_as_float(f2tf32(kv.y));
                kv.z = __uint_as_float(f2tf32(kv.z));
                kv.w = __uint_as_float(f2tf32(kv.w));
                *(float4*)&Kc[r * KP + c4] = kv;
                float4 vv = *(float4*)&Vc[r * VP + c4];
                vv.x = __uint_as_float(f2tf32(vv.x));
                vv.y = __uint_as_float(f2tf32(vv.y));
                vv.z = __uint_as_float(f2tf32(vv.z));
                vv.w = __uint_as_float(f2tf32(vv.w));
                *(float4*)&Vc[r * VP + c4] = vv;
            }
        }
        __syncthreads();

        if (ch > cw) continue;

        const float* Kc = Ks + (ch & 1) * CHK * KP;
        const float* Vc = Vs + (ch & 1) * CHK * VP;
        const int s0 = ch * CHK;
        const int ntmax = min(7, (r0 + 15 - s0) >> 3);
        const bool full = (s0 + CHK - 1 <= r0);

        float sc[8][4];
#pragma unroll
        for (int nt = 0; nt < 8; nt++)
            if (nt <= ntmax) { sc[nt][0] = 0; sc[nt][1] = 0; sc[nt][2] = 0; sc[nt][3] = 0; }
#pragma unroll
        for (int kc = 0; kc < 8; kc++) {
            const int kb = kc * 8;
#pragma unroll
            for (int nt = 0; nt < 8; nt++) {
                if (nt <= ntmax) {
                    unsigned bfr[2];
                    int krow = nt * 8 + g;
                    bfr[0] = __float_as_uint(Kc[krow * KP + kb + tig]);
                    bfr[1] = __float_as_uint(Kc[krow * KP + kb + tig + 4]);
                    mma_tf32(sc[nt], qf[kc], bfr);
                }
            }
        }

        float cm0 = -1e30f, cm1 = -1e30f;
#pragma unroll
        for (int nt = 0; nt < 8; nt++) {
            if (nt <= ntmax) {
                if (full) {
                    sc[nt][0] *= c2; sc[nt][1] *= c2; sc[nt][2] *= c2; sc[nt][3] *= c2;
                } else {
                    const int colb = s0 + nt * 8 + 2 * tig;
                    sc[nt][0] = (colb <= rg0) ? sc[nt][0] * c2 : -1e30f;
                    sc[nt][1] = (colb + 1 <= rg0) ? sc[nt][1] * c2 : -1e30f;
                    sc[nt][2] = (colb <= rg1) ? sc[nt][2] * c2 : -1e30f;
                    sc[nt][3] = (colb + 1 <= rg1) ? sc[nt][3] * c2 : -1e30f;
                }
                cm0 = fmaxf(cm0, fmaxf(sc[nt][0], sc[nt][1]));
                cm1 = fmaxf(cm1, fmaxf(sc[nt][2], sc[nt][3]));
            }
        }
        cm0 = fmaxf(cm0, __shfl_xor_sync(0xffffffffu, cm0, 1));
        cm0 = fmaxf(cm0, __shfl_xor_sync(0xffffffffu, cm0, 2));
        cm1 = fmaxf(cm1, __shfl_xor_sync(0xffffffffu, cm1, 1));
        cm1 = fmaxf(cm1, __shfl_xor_sync(0xffffffffu, cm1, 2));

        const float nm0 = fmaxf(mt0, cm0);
        const float nm1 = fmaxf(mt1, cm1);
        const float f0 = ex2(mt0 - nm0);
        const float f1 = ex2(mt1 - nm1);
        mt0 = nm0; mt1 = nm1;
        l0 *= f0; l1 *= f1;
#pragma unroll
        for (int nt = 0; nt < 8; nt++) {
            o[nt][0] *= f0; o[nt][1] *= f0; o[nt][2] *= f1; o[nt][3] *= f1;
        }

        __syncwarp();
#pragma unroll
        for (int nt = 0; nt < 8; nt++) {
            if (nt <= ntmax) {
                float p0 = ex2(sc[nt][0] - nm0);
                float p1 = ex2(sc[nt][1] - nm0);
                float p2 = ex2(sc[nt][2] - nm1);
                float p3 = ex2(sc[nt][3] - nm1);
                l0 += p0 + p1;
                l1 += p2 + p3;
                int cb = nt * 8 + 2 * tig;
                *(float2*)&Pw[g * PP + cb] =
                    make_float2(__uint_as_float(f2tf32(p0)), __uint_as_float(f2tf32(p1)));
                *(float2*)&Pw[(g + 8) * PP + cb] =
                    make_float2(__uint_as_float(f2tf32(p2)), __uint_as_float(f2tf32(p3)));
            }
        }
        __syncwarp();

#pragma unroll
        for (int kc = 0; kc < 8; kc++) {
            if (kc <= ntmax) {
                const int kb = kc * 8;
                unsigned a[4];
                a[0] = __float_as_uint(Pw[g * PP + kb + tig]);
                a[1] = __float_as_uint(Pw[(g + 8) * PP + kb + tig]);
                a[2] = __float_as_uint(Pw[g * PP + kb + tig + 4]);
                a[3] = __float_as_uint(Pw[(g + 8) * PP + kb + tig + 4]);
                const int vr0 = kb + tig;
                const int vr1 = kb + tig + 4;
#pragma unroll
                for (int nt = 0; nt < 8; nt++) {
                    unsigned bfr[2];
                    bfr[0] = __float_as_uint(Vc[vr0 * VP + nt * 8 + g]);
                    bfr[1] = __float_as_uint(Vc[vr1 * VP + nt * 8 + g]);
                    mma_tf32(o[nt], a, bfr);
                }
            }
        }
    }

    l0 += __shfl_xor_sync(0xffffffffu, l0, 1);
    l0 += __shfl_xor_sync(0xffffffffu, l0, 2);
    l1 += __shfl_xor_sync(0xffffffffu, l1, 1);
    l1 += __shfl_xor_sync(0xffffffffu, l1, 2);
    const float inv0 = __frcp_rn(l0);
    const float inv1 = __frcp_rn(l1);

#pragma unroll
    for (int nt = 0; nt < 8; nt++) {
        int cb = nt * 8 + 2 * tig;
        *(float2*)&ob[(size_t)rg0 * HH + cb] = make_float2(o[nt][0] * inv0, o[nt][1] * inv0);
        *(float2*)&ob[(size_t)rg1 * HH + cb] = make_float2(o[nt][2] * inv1, o[nt][3] * inv1);
    }
}

// ---------------------------------------------------------------------------
extern "C" void kernel_launch(void* const* d_in, const int* in_sizes, int n_in,
                              void* d_out, int out_size) {
    const float* x = (const float*)d_in[0];
    const float* y = (const float*)d_in[1];
    const float* Wq = (const float*)d_in[2];
    const float* Wk = (const float*)d_in[3];
    const float* Wv = (const float*)d_in[4];
    float* out = (float*)d_out;

    float* gq;   cudaGetSymbolAddress((void**)&gq, g_q);
    float* gk;   cudaGetSymbolAddress((void**)&gk, g_k);
    float* gv;   cudaGetSymbolAddress((void**)&gv, g_v);
    float* wpq;  cudaGetSymbolAddress((void**)&wpq, g_wpq);
    float* wpkv; cudaGetSymbolAddress((void**)&wpkv, g_wpkv);

    // proj smem (kv sizing): A 2*128*36 + B 2*256*16 floats = 69632 B -> 3 CTAs/SM
    const int smem_proj = (2 * 128 * 36 + 2 * 256 * 16) * 4;
    const int smem_attn = (2 * CHK * KP + 2 * CHK * VP + 8 * 16 * PP) * 4;     // 106496

    static bool attr_set = false;
    if (!attr_set) {
        cudaFuncSetAttribute(proj_all_kernel, cudaFuncAttributeMaxDynamicSharedMemorySize, smem_proj);
        cudaFuncSetAttribute(attn_kernel, cudaFuncAttributeMaxDynamicSharedMemorySize, smem_attn);
        attr_set = true;
    }

    wpack_kernel<<<192, 256>>>(Wq, Wk, Wv);
    proj_all_kernel<<<1024, 256, smem_proj>>>(x, y, wpq, wpkv, gq, gk, gv);
    attn_kernel<<<2 * BB, 256, smem_attn>>>(out);
}

// round 14
// speedup vs baseline: 1.8467x; 1.0354x over previous
#include <cuda_runtime.h>
#include <math.h>
#include <stdint.h>

// Problem shape (fixed)
#define BB 256
#define TT 256
#define CC 512
#define HH 64

// Scratch (device globals: no allocation allowed)
// g_q/g_k/g_v hold rna-tf32-rounded projection outputs (attn consumes raw bits).
__device__ float g_q[BB * TT * HH];
__device__ float g_k[BB * TT * HH];
__device__ float g_v[BB * TT * HH];
// Fragment-order packed weights (rna-tf32 applied):
//   index ((k8 * NTC + ntile) * 32 + lane) * 2 + j
//   holds W^T[n = ntile*8 + (lane>>2)][k = k8*8 + (lane&3) + 4*j]
__device__ float g_wpq[64 * 8 * 32 * 2];     // q:  NTC=8  (N=64)
__device__ float g_wpkv[64 * 16 * 32 * 2];   // kv: NTC=16 (N=128)

__device__ __forceinline__ unsigned f2tf32(float f) {
    unsigned r;
    asm("cvt.rna.tf32.f32 %0, %1;" : "=r"(r) : "f"(f));
    return r;
}

__device__ __forceinline__ float ex2(float x) {
    float r;
    asm("ex2.approx.ftz.f32 %0, %1;" : "=f"(r) : "f"(x));
    return r;
}

__device__ __forceinline__ void mma_tf32(float c[4], const unsigned a[4], const unsigned b[2]) {
    asm volatile(
        "mma.sync.aligned.m16n8k8.row.col.f32.tf32.tf32.f32 "
        "{%0,%1,%2,%3}, {%4,%5,%6,%7}, {%8,%9}, {%0,%1,%2,%3};\n"
        : "+f"(c[0]), "+f"(c[1]), "+f"(c[2]), "+f"(c[3])
        : "r"(a[0]), "r"(a[1]), "r"(a[2]), "r"(a[3]), "r"(b[0]), "r"(b[1]));
}

__device__ __forceinline__ void cp_async16(void* smem_dst, const void* gmem_src) {
    uint32_t d = (uint32_t)__cvta_generic_to_shared(smem_dst);
    asm volatile("cp.async.cg.shared.global [%0], [%1], 16;\n" :: "r"(d), "l"(gmem_src));
}
__device__ __forceinline__ void cp_commit() { asm volatile("cp.async.commit_group;\n"); }

// ---------------------------------------------------------------------------
// Weight pack prepass: fragment-order, rna-tf32. (unchanged R13)
// ---------------------------------------------------------------------------
__global__ void wpack_kernel(const float* __restrict__ Wq,
                             const float* __restrict__ Wk,
                             const float* __restrict__ Wv) {
    const int nq = 64 * 8 * 32 * 2;       // 32768
    int i = blockIdx.x * 256 + threadIdx.x;
    const int total = nq + 64 * 16 * 32 * 2;
    for (; i < total; i += gridDim.x * 256) {
        if (i < nq) {
            int j = i & 1;
            int lane = (i >> 1) & 31;
            int nt = (i >> 6) & 7;
            int k8 = i >> 9;
            int n = nt * 8 + (lane >> 2);
            int k = k8 * 8 + (lane & 3) + 4 * j;
            g_wpq[i] = __uint_as_float(f2tf32(Wq[k * 64 + n]));
        } else {
            int p = i - nq;
            int j = p & 1;
            int lane = (p >> 1) & 31;
            int nt = (p >> 6) & 15;
            int k8 = p >> 10;
            int n = nt * 8 + (lane >> 2);
            int k = k8 * 8 + (lane & 3) + 4 * j;
            float v = (n < 64) ? Wk[k * 64 + n] : Wv[k * 64 + (n - 64)];
            g_wpkv[p] = __uint_as_float(f2tf32(v));
        }
    }
}

// ---------------------------------------------------------------------------
// Projection GEMM (R13 body). R14 delta: epilogue stores rna-tf32-rounded
// accumulators (the exact values attn's old convert pass produced).
// ---------------------------------------------------------------------------
template <int BN>
__device__ __forceinline__ void proj_body(const float* __restrict__ A,
                                          const float* __restrict__ WP,
                                          float* __restrict__ C0,
                                          float* __restrict__ C1,
                                          int blk) {
    constexpr int APITCH = 36;
    constexpr int NTC = BN / 8;
    constexpr int WN = BN / 2;
    constexpr int NT = WN / 8;
    constexpr int NK = CC / 32;
    constexpr int BSTRIDE = 256 * NTC;
    constexpr int BCH = (BSTRIDE / 4) / 256;

    extern __shared__ float smraw[];
    float* Asf = smraw;                        // [2][128][APITCH]
    float* Bsf = smraw + 2 * 128 * APITCH;     // [2][BSTRIDE]

    const int tid = threadIdx.x;
    const int wid = tid >> 5;
    const int lane = tid & 31;
    const int wm = wid & 3;
    const int wn = wid >> 2;
    const int g = lane >> 2;
    const int tig = lane & 3;
    const int m0 = blk * 128;

    auto load_tile = [&](int st, int t) {
        float* As = Asf + st * 128 * APITCH;
        float* Bs = Bsf + st * BSTRIDE;
        const int k0 = t * 32;
#pragma unroll
        for (int l = 0; l < 4; l++) {
            int idx = tid + l * 256;
            int r = idx >> 3;
            int c4 = (idx & 7) << 2;
            cp_async16(&As[r * APITCH + c4], &A[(size_t)(m0 + r) * CC + k0 + c4]);
        }
        const float* src = WP + (size_t)t * BSTRIDE;
#pragma unroll
        for (int l = 0; l < BCH; l++) {
            int c = tid + l * 256;
            cp_async16(&Bs[c * 4], &src[c * 4]);
        }
        cp_commit();
    };

    float c[2][NT][4];
#pragma unroll
    for (int mt = 0; mt < 2; mt++)
#pragma unroll
        for (int nt = 0; nt < NT; nt++)
#pragma unroll
            for (int i = 0; i < 4; i++) c[mt][nt][i] = 0.0f;

    load_tile(0, 0);

    for (int t = 0; t < NK; t++) {
        if (t + 1 < NK) {
            load_tile((t + 1) & 1, t + 1);
            asm volatile("cp.async.wait_group 1;\n");
        } else {
            asm volatile("cp.async.wait_group 0;\n");
        }
        __syncthreads();

        const float* As = Asf + (t & 1) * 128 * APITCH;
        const float* Bs = Bsf + (t & 1) * BSTRIDE;

#pragma unroll
        for (int ks = 0; ks < 4; ks++) {
            const int kb = ks * 8;
            unsigned af[2][4];
#pragma unroll
            for (int mt = 0; mt < 2; mt++) {
                int r = wm * 32 + mt * 16;
                af[mt][0] = f2tf32(As[(r + g) * APITCH + kb + tig]);
                af[mt][1] = f2tf32(As[(r + g + 8) * APITCH + kb + tig]);
                af[mt][2] = f2tf32(As[(r + g) * APITCH + kb + tig + 4]);
                af[mt][3] = f2tf32(As[(r + g + 8) * APITCH + kb + tig + 4]);
            }
            unsigned bf[NT][2];
#pragma unroll
            for (int nt = 0; nt < NT; nt++) {
                int tile_n = wn * NT + nt;
                float2 b2 = *(const float2*)&Bs[((ks * NTC + tile_n) * 32 + lane) * 2];
                bf[nt][0] = __float_as_uint(b2.x);
                bf[nt][1] = __float_as_uint(b2.y);
            }
#pragma unroll
            for (int mt = 0; mt < 2; mt++)
#pragma unroll
                for (int nt = 0; nt < NT; nt++) mma_tf32(c[mt][nt], af[mt], bf[nt]);
        }
        __syncthreads();
    }

    // Epilogue: rna-round outputs (consumed as tf32 operands by attn).
#pragma unroll
    for (int mt = 0; mt < 2; mt++) {
#pragma unroll
        for (int nt = 0; nt < NT; nt++) {
            int gcol = wn * WN + nt * 8 + 2 * tig;
            float* dst;
            int col;
            if (BN == 64) { dst = C0; col = gcol; }
            else { dst = (gcol < 64) ? C0 : C1; col = (gcol < 64) ? gcol : gcol - 64; }
            int row = m0 + wm * 32 + mt * 16 + g;
            *(float2*)&dst[(size_t)row * HH + col] =
                make_float2(__uint_as_float(f2tf32(c[mt][nt][0])),
                            __uint_as_float(f2tf32(c[mt][nt][1])));
            *(float2*)&dst[(size_t)(row + 8) * HH + col] =
                make_float2(__uint_as_float(f2tf32(c[mt][nt][2])),
                            __uint_as_float(f2tf32(c[mt][nt][3])));
        }
    }
}

// Merged: blocks [0,512) -> q = x@Wq; [512,1024) -> [k|v] = y@[Wk|Wv].
__global__ __launch_bounds__(256) void proj_all_kernel(const float* __restrict__ x,
                                                       const float* __restrict__ y,
                                                       const float* __restrict__ wpq,
                                                       const float* __restrict__ wpkv,
                                                       float* __restrict__ gq,
                                                       float* __restrict__ gk,
                                                       float* __restrict__ gv) {
    if (blockIdx.x < 512) proj_body<64>(x, wpq, gq, gq, blockIdx.x);
    else                  proj_body<128>(y, wpkv, gk, gv, blockIdx.x - 512);
}

// ---------------------------------------------------------------------------
// Flash attention. R14 delta vs R5: K/V/Q arrive pre-rounded (proj epilogue),
// so the per-chunk in-place convert pass and its barrier are DELETED.
// Pipeline: wait -> sync -> prefetch(ch+1) -> compute(ch). One sync per chunk.
// ---------------------------------------------------------------------------
#define KP 68
#define VP 72
#define PP 68
#define CHK 64

__global__ __launch_bounds__(256, 2) void attn_kernel(float* __restrict__ out) {
    extern __shared__ float sm[];
    float* Ks = sm;
    float* Vs = Ks + 2 * CHK * KP;
    float* Ps = Vs + 2 * CHK * VP;

    const int bx = blockIdx.x;
    const int b = bx >> 1;
    const int q0 = (bx & 1) * 128;
    const int tid = threadIdx.x;
    const int w = tid >> 5;
    const int lane = tid & 31;
    const int g = lane >> 2;
    const int tig = lane & 3;

    const float* __restrict__ Kg = g_k + (size_t)b * TT * HH;
    const float* __restrict__ Vg = g_v + (size_t)b * TT * HH;
    const float* __restrict__ Qg = g_q + (size_t)b * TT * HH;
    float* __restrict__ ob = out + (size_t)b * TT * HH;

    auto stage_load = [&](int ch) {
        float* Kc = Ks + (ch & 1) * CHK * KP;
        float* Vc = Vs + (ch & 1) * CHK * VP;
        const int s0 = ch * CHK;
#pragma unroll
        for (int l = 0; l < 4; l++) {
            int idx = tid + l * 256;
            int r = idx >> 4;
            int c4 = (idx & 15) << 2;
            cp_async16(&Kc[r * KP + c4], &Kg[(size_t)(s0 + r) * HH + c4]);
            cp_async16(&Vc[r * VP + c4], &Vg[(size_t)(s0 + r) * HH + c4]);
        }
        cp_commit();
    };

    stage_load(0);

    const int r0 = q0 + w * 16;
    const int rg0 = r0 + g;
    const int rg1 = r0 + g + 8;
    unsigned qf[8][4];
#pragma unroll
    for (int kc = 0; kc < 8; kc++) {
        const int kb = kc * 8;
        qf[kc][0] = __float_as_uint(Qg[(size_t)rg0 * HH + kb + tig]);
        qf[kc][1] = __float_as_uint(Qg[(size_t)rg1 * HH + kb + tig]);
        qf[kc][2] = __float_as_uint(Qg[(size_t)rg0 * HH + kb + tig + 4]);
        qf[kc][3] = __float_as_uint(Qg[(size_t)rg1 * HH + kb + tig + 4]);
    }

    float* Pw = Ps + w * 16 * PP;
    const float c2 = 0.125f * 1.44269504089f;

    float o[8][4];
#pragma unroll
    for (int nt = 0; nt < 8; nt++)
#pragma unroll
        for (int j = 0; j < 4; j++) o[nt][j] = 0.0f;

    float mt0 = -1e30f, mt1 = -1e30f;
    float l0 = 0.0f, l1 = 0.0f;

    const int CB = (q0 + 127) >> 6;
    const int cw = (r0 + 15) >> 6;

    for (int ch = 0; ch <= CB; ch++) {
        asm volatile("cp.async.wait_group 0;\n");
        __syncthreads();
        if (ch < CB) stage_load(ch + 1);

        if (ch > cw) continue;

        const float* Kc = Ks + (ch & 1) * CHK * KP;
        const float* Vc = Vs + (ch & 1) * CHK * VP;
        const int s0 = ch * CHK;
        const int ntmax = min(7, (r0 + 15 - s0) >> 3);
        const bool full = (s0 + CHK - 1 <= r0);

        float sc[8][4];
#pragma unroll
        for (int nt = 0; nt < 8; nt++)
            if (nt <= ntmax) { sc[nt][0] = 0; sc[nt][1] = 0; sc[nt][2] = 0; sc[nt][3] = 0; }
#pragma unroll
        for (int kc = 0; kc < 8; kc++) {
            const int kb = kc * 8;
#pragma unroll
            for (int nt = 0; nt < 8; nt++) {
                if (nt <= ntmax) {
                    unsigned bfr[2];
                    int krow = nt * 8 + g;
                    bfr[0] = __float_as_uint(Kc[krow * KP + kb + tig]);
                    bfr[1] = __float_as_uint(Kc[krow * KP + kb + tig + 4]);
                    mma_tf32(sc[nt], qf[kc], bfr);
                }
            }
        }

        float cm0 = -1e30f, cm1 = -1e30f;
#pragma unroll
        for (int nt = 0; nt < 8; nt++) {
            if (nt <= ntmax) {
                if (full) {
                    sc[nt][0] *= c2; sc[nt][1] *= c2; sc[nt][2] *= c2; sc[nt][3] *= c2;
                } else {
                    const int colb = s0 + nt * 8 + 2 * tig;
                    sc[nt][0] = (colb <= rg0) ? sc[nt][0] * c2 : -1e30f;
                    sc[nt][1] = (colb + 1 <= rg0) ? sc[nt][1] * c2 : -1e30f;
                    sc[nt][2] = (colb <= rg1) ? sc[nt][2] * c2 : -1e30f;
                    sc[nt][3] = (colb + 1 <= rg1) ? sc[nt][3] * c2 : -1e30f;
                }
                cm0 = fmaxf(cm0, fmaxf(sc[nt][0], sc[nt][1]));
                cm1 = fmaxf(cm1, fmaxf(sc[nt][2], sc[nt][3]));
            }
        }
        cm0 = fmaxf(cm0, __shfl_xor_sync(0xffffffffu, cm0, 1));
        cm0 = fmaxf(cm0, __shfl_xor_sync(0xffffffffu, cm0, 2));
        cm1 = fmaxf(cm1, __shfl_xor_sync(0xffffffffu, cm1, 1));
        cm1 = fmaxf(cm1, __shfl_xor_sync(0xffffffffu, cm1, 2));

        const float nm0 = fmaxf(mt0, cm0);
        const float nm1 = fmaxf(mt1, cm1);
        const float f0 = ex2(mt0 - nm0);
        const float f1 = ex2(mt1 - nm1);
        mt0 = nm0; mt1 = nm1;
        l0 *= f0; l1 *= f1;
#pragma unroll
        for (int nt = 0; nt < 8; nt++) {
            o[nt][0] *= f0; o[nt][1] *= f0; o[nt][2] *= f1; o[nt][3] *= f1;
        }

        __syncwarp();
#pragma unroll
        for (int nt = 0; nt < 8; nt++) {
            if (nt <= ntmax) {
                float p0 = ex2(sc[nt][0] - nm0);
                float p1 = ex2(sc[nt][1] - nm0);
                float p2 = ex2(sc[nt][2] - nm1);
                float p3 = ex2(sc[nt][3] - nm1);
                l0 += p0 + p1;
                l1 += p2 + p3;
                int cb = nt * 8 + 2 * tig;
                *(float2*)&Pw[g * PP + cb] =
                    make_float2(__uint_as_float(f2tf32(p0)), __uint_as_float(f2tf32(p1)));
                *(float2*)&Pw[(g + 8) * PP + cb] =
                    make_float2(__uint_as_float(f2tf32(p2)), __uint_as_float(f2tf32(p3)));
            }
        }
        __syncwarp();

#pragma unroll
        for (int kc = 0; kc < 8; kc++) {
            if (kc <= ntmax) {
                const int kb = kc * 8;
                unsigned a[4];
                a[0] = __float_as_uint(Pw[g * PP + kb + tig]);
                a[1] = __float_as_uint(Pw[(g + 8) * PP + kb + tig]);
                a[2] = __float_as_uint(Pw[g * PP + kb + tig + 4]);
                a[3] = __float_as_uint(Pw[(g + 8) * PP + kb + tig + 4]);
                const int vr0 = kb + tig;
                const int vr1 = kb + tig + 4;
#pragma unroll
                for (int nt = 0; nt < 8; nt++) {
                    unsigned bfr[2];
                    bfr[0] = __float_as_uint(Vc[vr0 * VP + nt * 8 + g]);
                    bfr[1] = __float_as_uint(Vc[vr1 * VP + nt * 8 + g]);
                    mma_tf32(o[nt], a, bfr);
                }
            }
        }
    }

    l0 += __shfl_xor_sync(0xffffffffu, l0, 1);
    l0 += __shfl_xor_sync(0xffffffffu, l0, 2);
    l1 += __shfl_xor_sync(0xffffffffu, l1, 1);
    l1 += __shfl_xor_sync(0xffffffffu, l1, 2);
    const float inv0 = __frcp_rn(l0);
    const float inv1 = __frcp_rn(l1);

#pragma unroll
    for (int nt = 0; nt < 8; nt++) {
        int cb = nt * 8 + 2 * tig;
        *(float2*)&ob[(size_t)rg0 * HH + cb] = make_float2(o[nt][0] * inv0, o[nt][1] * inv0);
        *(float2*)&ob[(size_t)rg1 * HH + cb] = make_float2(o[nt][2] * inv1, o[nt][3] * inv1);
    }
}

// ---------------------------------------------------------------------------
extern "C" void kernel_launch(void* const* d_in, const int* in_sizes, int n_in,
                              void* d_out, int out_size) {
    const float* x = (const float*)d_in[0];
    const float* y = (const float*)d_in[1];
    const float* Wq = (const float*)d_in[2];
    const float* Wk = (const float*)d_in[3];
    const float* Wv = (const float*)d_in[4];
    float* out = (float*)d_out;

    float* gq;   cudaGetSymbolAddress((void**)&gq, g_q);
    float* gk;   cudaGetSymbolAddress((void**)&gk, g_k);
    float* gv;   cudaGetSymbolAddress((void**)&gv, g_v);
    float* wpq;  cudaGetSymbolAddress((void**)&wpq, g_wpq);
    float* wpkv; cudaGetSymbolAddress((void**)&wpkv, g_wpkv);

    const int smem_proj = (2 * 128 * 36 + 2 * 256 * 16) * 4;                   // 69632
    const int smem_attn = (2 * CHK * KP + 2 * CHK * VP + 8 * 16 * PP) * 4;     // 106496

    static bool attr_set = false;
    if (!attr_set) {
        cudaFuncSetAttribute(proj_all_kernel, cudaFuncAttributeMaxDynamicSharedMemorySize, smem_proj);
        cudaFuncSetAttribute(attn_kernel, cudaFuncAttributeMaxDynamicSharedMemorySize, smem_attn);
        attr_set = true;
    }

    wpack_kernel<<<192, 256>>>(Wq, Wk, Wv);
    proj_all_kernel<<<1024, 256, smem_proj>>>(x, y, wpq, wpkv, gq, gk, gv);
    attn_kernel<<<2 * BB, 256, smem_attn>>>(out);
}